// round 2
// baseline (speedup 1.0000x reference)
#include <cuda_runtime.h>
#include <math.h>

// ---------------------------------------------------------------------------
// AutoEncoder: x[8192,1024] -> relu(2048) -> relu(2048) -> sigmoid(64)
//                           -> relu(2048) -> relu(2048) -> linear(1024)
// Output: concat(control [8192*64], state [8192*1024]) as float32.
// Round 1: fp32 SIMT tiled GEMM baseline (exact math, no precision risk).
// ---------------------------------------------------------------------------

#define BATCH 8192
#define HDIM  2048

#define BM 128
#define BN 128
#define BK 16
#define TM 8
#define TN 8
#define THREADS 256

// Scratch ping-pong buffers (device globals: allocation-free per harness rules)
__device__ float g_buf0[(size_t)BATCH * HDIM];
__device__ float g_buf1[(size_t)BATCH * HDIM];

// act: 0 = linear, 1 = relu, 2 = sigmoid
__global__ __launch_bounds__(THREADS)
void gemm_bias_act(const float* __restrict__ A,   // [M,K] row-major
                   const float* __restrict__ B,   // [K,N] row-major
                   const float* __restrict__ bias,// [N]
                   float* __restrict__ C,         // [M,N] row-major
                   int M, int N, int K, int act)
{
    __shared__ float As[BK][BM];   // transposed A tile: As[k][m]
    __shared__ float Bs[BK][BN];   // Bs[k][n]

    const int tid  = threadIdx.x;
    const int row0 = blockIdx.y * BM;
    const int col0 = blockIdx.x * BN;

    const int tx = tid & 15;   // 16 thread cols
    const int ty = tid >> 4;   // 16 thread rows

    float acc[TM][TN];
#pragma unroll
    for (int i = 0; i < TM; i++)
#pragma unroll
        for (int j = 0; j < TN; j++) acc[i][j] = 0.0f;

    for (int k0 = 0; k0 < K; k0 += BK) {
        // --- load A tile: BM x BK = 2048 floats = 512 float4, 2 per thread ---
#pragma unroll
        for (int i = 0; i < 2; i++) {
            int v  = tid + i * THREADS;      // 0..511
            int r  = v >> 2;                 // 0..127 (row within tile)
            int kc = (v & 3) * 4;            // 0,4,8,12 (k within tile)
            float4 av = *reinterpret_cast<const float4*>(
                &A[(size_t)(row0 + r) * K + (k0 + kc)]);
            As[kc + 0][r] = av.x;
            As[kc + 1][r] = av.y;
            As[kc + 2][r] = av.z;
            As[kc + 3][r] = av.w;
        }
        // --- load B tile: BK x BN = 2048 floats = 512 float4, 2 per thread ---
#pragma unroll
        for (int i = 0; i < 2; i++) {
            int v  = tid + i * THREADS;
            int kr = v >> 5;                 // 0..15
            int c  = (v & 31) * 4;           // 0..124
            int gc = col0 + c;
            float4 bv;
            if (gc < N)
                bv = *reinterpret_cast<const float4*>(
                    &B[(size_t)(k0 + kr) * N + gc]);
            else
                bv = make_float4(0.f, 0.f, 0.f, 0.f);
            *reinterpret_cast<float4*>(&Bs[kr][c]) = bv;
        }
        __syncthreads();

        // --- compute ---
#pragma unroll
        for (int k = 0; k < BK; k++) {
            float ra[TM], rb[TN];
#pragma unroll
            for (int i = 0; i < TM; i += 4) {
                float4 v = *reinterpret_cast<const float4*>(&As[k][ty * TM + i]);
                ra[i+0] = v.x; ra[i+1] = v.y; ra[i+2] = v.z; ra[i+3] = v.w;
            }
#pragma unroll
            for (int j = 0; j < TN; j += 4) {
                float4 v = *reinterpret_cast<const float4*>(&Bs[k][tx * TN + j]);
                rb[j+0] = v.x; rb[j+1] = v.y; rb[j+2] = v.z; rb[j+3] = v.w;
            }
#pragma unroll
            for (int i = 0; i < TM; i++)
#pragma unroll
                for (int j = 0; j < TN; j++)
                    acc[i][j] = fmaf(ra[i], rb[j], acc[i][j]);
        }
        __syncthreads();
    }

    // --- epilogue: bias + activation, vectorized stores ---
#pragma unroll
    for (int i = 0; i < TM; i++) {
        int r = row0 + ty * TM + i;
#pragma unroll
        for (int j = 0; j < TN; j += 4) {
            int c = col0 + tx * TN + j;
            if (c < N) {
                float4 v;
                v.x = acc[i][j+0] + bias[c+0];
                v.y = acc[i][j+1] + bias[c+1];
                v.z = acc[i][j+2] + bias[c+2];
                v.w = acc[i][j+3] + bias[c+3];
                if (act == 1) {
                    v.x = fmaxf(v.x, 0.f); v.y = fmaxf(v.y, 0.f);
                    v.z = fmaxf(v.z, 0.f); v.w = fmaxf(v.w, 0.f);
                } else if (act == 2) {
                    v.x = 1.0f / (1.0f + expf(-v.x));
                    v.y = 1.0f / (1.0f + expf(-v.y));
                    v.z = 1.0f / (1.0f + expf(-v.z));
                    v.w = 1.0f / (1.0f + expf(-v.w));
                }
                *reinterpret_cast<float4*>(&C[(size_t)r * N + c]) = v;
            }
        }
    }
}

static inline void launch_layer(const float* A, const float* W, const float* b,
                                float* C, int M, int N, int K, int act)
{
    dim3 grid((N + BN - 1) / BN, M / BM);
    gemm_bias_act<<<grid, THREADS>>>(A, W, b, C, M, N, K, act);
}

extern "C" void kernel_launch(void* const* d_in, const int* in_sizes, int n_in,
                              void* d_out, int out_size)
{
    // Input order: x, We1, be1, We2, be2, We3, be3, Wd1, bd1, Wd2, bd2, Wd3, bd3
    const float* x   = (const float*)d_in[0];
    const float* We1 = (const float*)d_in[1];
    const float* be1 = (const float*)d_in[2];
    const float* We2 = (const float*)d_in[3];
    const float* be2 = (const float*)d_in[4];
    const float* We3 = (const float*)d_in[5];
    const float* be3 = (const float*)d_in[6];
    const float* Wd1 = (const float*)d_in[7];
    const float* bd1 = (const float*)d_in[8];
    const float* Wd2 = (const float*)d_in[9];
    const float* bd2 = (const float*)d_in[10];
    const float* Wd3 = (const float*)d_in[11];
    const float* bd3 = (const float*)d_in[12];

    float* out = (float*)d_out;
    float* control = out;                          // [8192, 64]
    float* state   = out + (size_t)BATCH * 64;     // [8192, 1024]

    float *buf0 = nullptr, *buf1 = nullptr;
    cudaGetSymbolAddress((void**)&buf0, g_buf0);
    cudaGetSymbolAddress((void**)&buf1, g_buf1);

    // Encoder
    launch_layer(x,    We1, be1, buf0,    BATCH, HDIM, 1024, 1); // relu
    launch_layer(buf0, We2, be2, buf1,    BATCH, HDIM, HDIM, 1); // relu
    launch_layer(buf1, We3, be3, control, BATCH,   64, HDIM, 2); // sigmoid

    // Decoder
    launch_layer(control, Wd1, bd1, buf0, BATCH, HDIM,   64, 1); // relu
    launch_layer(buf0,    Wd2, bd2, buf1, BATCH, HDIM, HDIM, 1); // relu
    launch_layer(buf1,    Wd3, bd3, state,BATCH, 1024, HDIM, 0); // linear
}

// round 4
// speedup vs baseline: 2.8689x; 2.8689x over previous
#include <cuda_runtime.h>
#include <cuda_bf16.h>
#include <cstdint>
#include <math.h>

// ============================================================================
// AutoEncoder via mma.sync (HMMA, PTX-portable on sm_103), bf16 hi/lo split.
//   x[8192,1024] -> relu(2048) -> relu(2048) -> sigmoid(64)
//                -> relu(2048) -> relu(2048) -> linear(1024)
// Out: concat(control [8192*64], state [8192*1024]) fp32.
// ============================================================================

#define BATCH 8192

// ---------------------------------------------------------------------------
// PTX helpers (all portable: sm_80+ instructions only)
// ---------------------------------------------------------------------------
__device__ __forceinline__ uint32_t smem_u32(const void* p) {
    uint32_t a;
    asm("{ .reg .u64 t; cvta.to.shared.u64 t, %1; cvt.u32.u64 %0, t; }"
        : "=r"(a) : "l"(p));
    return a;
}
__device__ __forceinline__ void cp_async16(uint32_t dst, const void* src) {
    asm volatile("cp.async.cg.shared.global [%0], [%1], 16;" :: "r"(dst), "l"(src));
}
__device__ __forceinline__ void cp_commit() {
    asm volatile("cp.async.commit_group;" ::: "memory");
}
template <int N> __device__ __forceinline__ void cp_wait() {
    asm volatile("cp.async.wait_group %0;" :: "n"(N) : "memory");
}
__device__ __forceinline__ void ldsm4(uint32_t* r, uint32_t a) {
    asm volatile("ldmatrix.sync.aligned.m8n8.x4.shared.b16 {%0,%1,%2,%3}, [%4];"
                 : "=r"(r[0]), "=r"(r[1]), "=r"(r[2]), "=r"(r[3]) : "r"(a));
}
__device__ __forceinline__ void mma16816(float* d, const uint32_t* a, const uint32_t* b) {
    asm volatile("mma.sync.aligned.m16n8k16.row.col.f32.bf16.bf16.f32 "
                 "{%0,%1,%2,%3}, {%4,%5,%6,%7}, {%8,%9}, {%0,%1,%2,%3};"
                 : "+f"(d[0]), "+f"(d[1]), "+f"(d[2]), "+f"(d[3])
                 : "r"(a[0]), "r"(a[1]), "r"(a[2]), "r"(a[3]),
                   "r"(b[0]), "r"(b[1]));
}
// 64B logical rows packed pairwise into 128B atoms + SW128 XOR swizzle:
// conflict-free ldmatrix for 8 consecutive rows at any 16B chunk.
__device__ __forceinline__ uint32_t tile_off(int r, int c) {
    uint32_t o = ((uint32_t)(r >> 1) << 7) + ((uint32_t)(r & 1) << 6) +
                 ((uint32_t)c << 4);
    return o ^ ((o >> 3) & 0x70);
}

// ---------------------------------------------------------------------------
// Device global scratch (allocation-free per harness rules)
// ---------------------------------------------------------------------------
__device__ __align__(16) __nv_bfloat16 g_bufA_h[(size_t)BATCH * 2048];
__device__ __align__(16) __nv_bfloat16 g_bufA_l[(size_t)BATCH * 2048];
__device__ __align__(16) __nv_bfloat16 g_bufB_h[(size_t)BATCH * 2048];
__device__ __align__(16) __nv_bfloat16 g_bufB_l[(size_t)BATCH * 2048];
__device__ __align__(16) __nv_bfloat16 g_ctrl_h[(size_t)BATCH * 64];
__device__ __align__(16) __nv_bfloat16 g_ctrl_l[(size_t)BATCH * 64];

// packed transposed weights W^T [N,K], hi/lo
#define OFF_We1 0u
#define OFF_We2 (OFF_We1 + 2048u*1024u)
#define OFF_We3 (OFF_We2 + 2048u*2048u)
#define OFF_Wd1 (OFF_We3 + 64u*2048u)
#define OFF_Wd2 (OFF_Wd1 + 2048u*64u)
#define OFF_Wd3 (OFF_Wd2 + 2048u*2048u)
#define W_TOTAL (OFF_Wd3 + 1024u*2048u)
__device__ __align__(16) __nv_bfloat16 g_Wh[W_TOTAL];
__device__ __align__(16) __nv_bfloat16 g_Wl[W_TOTAL];

// ---------------------------------------------------------------------------
// Prep kernels
// ---------------------------------------------------------------------------
__global__ void split_convert(const float* __restrict__ X,
                              __nv_bfloat16* __restrict__ H,
                              __nv_bfloat16* __restrict__ L, int n4) {
    int i = blockIdx.x * blockDim.x + threadIdx.x;
    if (i >= n4) return;
    float4 x = reinterpret_cast<const float4*>(X)[i];
    __nv_bfloat16 h0 = __float2bfloat16(x.x), h1 = __float2bfloat16(x.y);
    __nv_bfloat16 h2 = __float2bfloat16(x.z), h3 = __float2bfloat16(x.w);
    __nv_bfloat16 l0 = __float2bfloat16(x.x - __bfloat162float(h0));
    __nv_bfloat16 l1 = __float2bfloat16(x.y - __bfloat162float(h1));
    __nv_bfloat16 l2 = __float2bfloat16(x.z - __bfloat162float(h2));
    __nv_bfloat16 l3 = __float2bfloat16(x.w - __bfloat162float(h3));
    reinterpret_cast<__nv_bfloat162*>(H)[i * 2 + 0] = __halves2bfloat162(h0, h1);
    reinterpret_cast<__nv_bfloat162*>(H)[i * 2 + 1] = __halves2bfloat162(h2, h3);
    reinterpret_cast<__nv_bfloat162*>(L)[i * 2 + 0] = __halves2bfloat162(l0, l1);
    reinterpret_cast<__nv_bfloat162*>(L)[i * 2 + 1] = __halves2bfloat162(l2, l3);
}

// W[K,N] fp32 -> Th/Tl[N,K] bf16 (transpose + split)
__global__ void transpose_split(const float* __restrict__ W,
                                __nv_bfloat16* __restrict__ Th,
                                __nv_bfloat16* __restrict__ Tl, int K, int N) {
    __shared__ float t[32][33];
    int k0 = blockIdx.x * 32, n0 = blockIdx.y * 32;
    int tx = threadIdx.x, ty = threadIdx.y;
    for (int r = ty; r < 32; r += 8)
        t[r][tx] = W[(size_t)(k0 + r) * N + n0 + tx];
    __syncthreads();
    for (int r = ty; r < 32; r += 8) {
        float v = t[tx][r];
        size_t o = (size_t)(n0 + r) * K + k0 + tx;
        __nv_bfloat16 h = __float2bfloat16(v);
        Th[o] = h;
        Tl[o] = __float2bfloat16(v - __bfloat162float(h));
    }
}

// ---------------------------------------------------------------------------
// mma.sync GEMM: C[M,N] = act(A[M,K] @ (W^T[N,K])^T + bias)
//  A, B as hi/lo bf16; 3 mma products (hh, hl, lh).
//  OUTMODE: 0 = f32 only, 1 = bf16 hi/lo pair only, 2 = both (after act)
// ---------------------------------------------------------------------------
template <int BM, int BN, int WARPS_M, int WARPS_N, int OUTMODE>
__global__ __launch_bounds__(256, 1)
void gemm_mma(const __nv_bfloat16* __restrict__ Ah, const __nv_bfloat16* __restrict__ Al,
              const __nv_bfloat16* __restrict__ Bh, const __nv_bfloat16* __restrict__ Bl,
              const float* __restrict__ bias,
              float* __restrict__ Cf,
              __nv_bfloat16* __restrict__ Ch, __nv_bfloat16* __restrict__ Cl,
              int N, int K, int act)
{
    constexpr int BK = 32;
    constexpr int WM = BM / WARPS_M, WN = BN / WARPS_N;
    constexpr int MW = WM / 16, NW = WN / 8;
    constexpr int ASZ = BM * 64;   // bytes per A operand per stage (32 bf16/row)
    constexpr int BSZ = BN * 64;
    constexpr int SSZ = 2 * ASZ + 2 * BSZ;

    extern __shared__ __align__(128) char sm[];
    const uint32_t sb = smem_u32(sm);
    const int tid = threadIdx.x, wid = tid >> 5, lid = tid & 31;
    const int row0 = blockIdx.y * BM, col0 = blockIdx.x * BN;
    const int KT = K / BK;

    const int wm0 = (wid % WARPS_M) * WM;
    const int wn0 = (wid / WARPS_M) * WN;
    const int mat = lid >> 3, mr = lid & 7;

    float acc[MW][NW][4];
#pragma unroll
    for (int i = 0; i < MW; i++)
#pragma unroll
        for (int j = 0; j < NW; j++)
#pragma unroll
            for (int q = 0; q < 4; q++) acc[i][j][q] = 0.0f;

    auto load_stage = [&](int kt, int s) {
        const uint32_t st = sb + s * SSZ;
        const int k0 = kt * BK;
#pragma unroll
        for (int ch = tid; ch < BM * 4; ch += 256) {
            int r = ch >> 2, c = ch & 3;
            size_t g = (size_t)(row0 + r) * K + k0 + c * 8;
            uint32_t so = st + tile_off(r, c);
            cp_async16(so, Ah + g);
            cp_async16(so + ASZ, Al + g);
        }
#pragma unroll
        for (int ch = tid; ch < BN * 4; ch += 256) {
            int r = ch >> 2, c = ch & 3;
            size_t g = (size_t)(col0 + r) * K + k0 + c * 8;
            uint32_t so = st + 2 * ASZ + tile_off(r, c);
            cp_async16(so, Bh + g);
            cp_async16(so + BSZ, Bl + g);
        }
        cp_commit();
    };

    // per-lane ldmatrix row indices (fixed); chunk varies with k
    int arow[MW], brow[NW / 2];
#pragma unroll
    for (int i = 0; i < MW; i++) arow[i] = wm0 + i * 16 + (mat & 1) * 8 + mr;
#pragma unroll
    for (int j = 0; j < NW / 2; j++) brow[j] = wn0 + j * 16 + (mat >> 1) * 8 + mr;

    load_stage(0, 0);

    for (int kt = 0; kt < KT; kt++) {
        const int s = kt & 1;
        if (kt + 1 < KT) { load_stage(kt + 1, s ^ 1); cp_wait<1>(); }
        else             { cp_wait<0>(); }
        __syncthreads();

        const uint32_t stA  = sb + s * SSZ;
        const uint32_t stAl = stA + ASZ;
        const uint32_t stB  = stA + 2 * ASZ;
        const uint32_t stBl = stB + BSZ;

#pragma unroll
        for (int ks = 0; ks < 2; ks++) {
            uint32_t ah[MW][4], al[MW][4], bh[NW][2], bl[NW][2];
#pragma unroll
            for (int i = 0; i < MW; i++) {
                uint32_t off = tile_off(arow[i], 2 * ks + (mat >> 1));
                ldsm4(ah[i], stA + off);
                ldsm4(al[i], stAl + off);
            }
#pragma unroll
            for (int j = 0; j < NW / 2; j++) {
                uint32_t off = tile_off(brow[j], 2 * ks + (mat & 1));
                uint32_t t[4];
                ldsm4(t, stB + off);
                bh[2 * j][0] = t[0]; bh[2 * j][1] = t[1];
                bh[2 * j + 1][0] = t[2]; bh[2 * j + 1][1] = t[3];
                ldsm4(t, stBl + off);
                bl[2 * j][0] = t[0]; bl[2 * j][1] = t[1];
                bl[2 * j + 1][0] = t[2]; bl[2 * j + 1][1] = t[3];
            }
#pragma unroll
            for (int i = 0; i < MW; i++)
#pragma unroll
                for (int j = 0; j < NW; j++) {
                    mma16816(acc[i][j], ah[i], bh[j]);  // hh
                    mma16816(acc[i][j], ah[i], bl[j]);  // hl
                    mma16816(acc[i][j], al[i], bh[j]);  // lh
                }
        }
        __syncthreads();
    }

    // ---- epilogue: bias + act + (f32 and/or bf16 hi/lo) ----
    const int lm = lid >> 2, ln2 = (lid & 3) * 2;
#pragma unroll
    for (int i = 0; i < MW; i++)
#pragma unroll
        for (int j = 0; j < NW; j++)
#pragma unroll
            for (int h = 0; h < 2; h++) {
                int gm = row0 + wm0 + i * 16 + h * 8 + lm;
                int gn = col0 + wn0 + j * 8 + ln2;
                float v0 = acc[i][j][2 * h + 0] + __ldg(bias + gn);
                float v1 = acc[i][j][2 * h + 1] + __ldg(bias + gn + 1);
                if (act == 1) { v0 = fmaxf(v0, 0.f); v1 = fmaxf(v1, 0.f); }
                else if (act == 2) {
                    v0 = 1.0f / (1.0f + expf(-v0));
                    v1 = 1.0f / (1.0f + expf(-v1));
                }
                size_t o = (size_t)gm * N + gn;
                if (OUTMODE == 0 || OUTMODE == 2)
                    *reinterpret_cast<float2*>(Cf + o) = make_float2(v0, v1);
                if (OUTMODE == 1 || OUTMODE == 2) {
                    __nv_bfloat16 h0 = __float2bfloat16(v0);
                    __nv_bfloat16 h1 = __float2bfloat16(v1);
                    __nv_bfloat16 l0 = __float2bfloat16(v0 - __bfloat162float(h0));
                    __nv_bfloat16 l1 = __float2bfloat16(v1 - __bfloat162float(h1));
                    *reinterpret_cast<__nv_bfloat162*>(Ch + o) = __halves2bfloat162(h0, h1);
                    *reinterpret_cast<__nv_bfloat162*>(Cl + o) = __halves2bfloat162(l0, l1);
                }
            }
}

// ---------------------------------------------------------------------------
// Host launch
// ---------------------------------------------------------------------------
extern "C" void kernel_launch(void* const* d_in, const int* in_sizes, int n_in,
                              void* d_out, int out_size) {
    const float* x   = (const float*)d_in[0];
    const float* We1 = (const float*)d_in[1];
    const float* be1 = (const float*)d_in[2];
    const float* We2 = (const float*)d_in[3];
    const float* be2 = (const float*)d_in[4];
    const float* We3 = (const float*)d_in[5];
    const float* be3 = (const float*)d_in[6];
    const float* Wd1 = (const float*)d_in[7];
    const float* bd1 = (const float*)d_in[8];
    const float* Wd2 = (const float*)d_in[9];
    const float* bd2 = (const float*)d_in[10];
    const float* Wd3 = (const float*)d_in[11];
    const float* bd3 = (const float*)d_in[12];

    float* out = (float*)d_out;
    float* control = out;
    float* state   = out + (size_t)BATCH * 64;

    __nv_bfloat16 *bufAh, *bufAl, *bufBh, *bufBl, *ctrlh, *ctrll, *Wh, *Wl;
    cudaGetSymbolAddress((void**)&bufAh, g_bufA_h);
    cudaGetSymbolAddress((void**)&bufAl, g_bufA_l);
    cudaGetSymbolAddress((void**)&bufBh, g_bufB_h);
    cudaGetSymbolAddress((void**)&bufBl, g_bufB_l);
    cudaGetSymbolAddress((void**)&ctrlh, g_ctrl_h);
    cudaGetSymbolAddress((void**)&ctrll, g_ctrl_l);
    cudaGetSymbolAddress((void**)&Wh, g_Wh);
    cudaGetSymbolAddress((void**)&Wl, g_Wl);

    constexpr int SMEM_BIG   = 2 * (2 * 128 * 64 + 2 * 128 * 64);  // 65536
    constexpr int SMEM_SMALL = 2 * (2 * 64 * 64 + 2 * 64 * 64);    // 32768
    cudaFuncSetAttribute(gemm_mma<128,128,4,2,0>, cudaFuncAttributeMaxDynamicSharedMemorySize, SMEM_BIG);
    cudaFuncSetAttribute(gemm_mma<128,128,4,2,1>, cudaFuncAttributeMaxDynamicSharedMemorySize, SMEM_BIG);
    cudaFuncSetAttribute(gemm_mma<64,64,4,2,2>,   cudaFuncAttributeMaxDynamicSharedMemorySize, SMEM_SMALL);

    // ---- prep: split x; transpose+split all weights ----
    {
        int n4 = BATCH * 1024 / 4;
        split_convert<<<(n4 + 255) / 256, 256>>>(x, bufBh, bufBl, n4);
    }
    dim3 tb(32, 8);
    transpose_split<<<dim3(1024/32, 2048/32), tb>>>(We1, Wh + OFF_We1, Wl + OFF_We1, 1024, 2048);
    transpose_split<<<dim3(2048/32, 2048/32), tb>>>(We2, Wh + OFF_We2, Wl + OFF_We2, 2048, 2048);
    transpose_split<<<dim3(2048/32, 64/32),   tb>>>(We3, Wh + OFF_We3, Wl + OFF_We3, 2048, 64);
    transpose_split<<<dim3(64/32, 2048/32),   tb>>>(Wd1, Wh + OFF_Wd1, Wl + OFF_Wd1, 64, 2048);
    transpose_split<<<dim3(2048/32, 2048/32), tb>>>(Wd2, Wh + OFF_Wd2, Wl + OFF_Wd2, 2048, 2048);
    transpose_split<<<dim3(2048/32, 1024/32), tb>>>(Wd3, Wh + OFF_Wd3, Wl + OFF_Wd3, 2048, 1024);

    // L1: x @ We1 -> relu -> bufA pair (N=2048, K=1024)
    gemm_mma<128,128,4,2,1><<<dim3(16, 64), 256, SMEM_BIG>>>(
        bufBh, bufBl, Wh + OFF_We1, Wl + OFF_We1, be1,
        nullptr, bufAh, bufAl, 2048, 1024, 1);
    // L2: bufA @ We2 -> relu -> bufB pair (N=2048, K=2048)
    gemm_mma<128,128,4,2,1><<<dim3(16, 64), 256, SMEM_BIG>>>(
        bufAh, bufAl, Wh + OFF_We2, Wl + OFF_We2, be2,
        nullptr, bufBh, bufBl, 2048, 2048, 1);
    // L3: bufB @ We3 -> sigmoid -> control f32 + ctrl pair (N=64, K=2048)
    gemm_mma<64,64,4,2,2><<<dim3(1, 128), 256, SMEM_SMALL>>>(
        bufBh, bufBl, Wh + OFF_We3, Wl + OFF_We3, be3,
        control, ctrlh, ctrll, 64, 2048, 2);
    // L4: ctrl @ Wd1 -> relu -> bufA pair (N=2048, K=64)
    gemm_mma<128,128,4,2,1><<<dim3(16, 64), 256, SMEM_BIG>>>(
        ctrlh, ctrll, Wh + OFF_Wd1, Wl + OFF_Wd1, bd1,
        nullptr, bufAh, bufAl, 2048, 64, 1);
    // L5: bufA @ Wd2 -> relu -> bufB pair (N=2048, K=2048)
    gemm_mma<128,128,4,2,1><<<dim3(16, 64), 256, SMEM_BIG>>>(
        bufAh, bufAl, Wh + OFF_Wd2, Wl + OFF_Wd2, bd2,
        nullptr, bufBh, bufBl, 2048, 2048, 1);
    // L6: bufB @ Wd3 -> state f32 (N=1024, K=2048)
    gemm_mma<128,128,4,2,0><<<dim3(8, 64), 256, SMEM_BIG>>>(
        bufBh, bufBl, Wh + OFF_Wd3, Wl + OFF_Wd3, bd3,
        state, nullptr, nullptr, 1024, 2048, 0);

    (void)in_sizes; (void)n_in; (void)out_size;
}

// round 5
// speedup vs baseline: 2.9862x; 1.0409x over previous
#include <cuda_runtime.h>
#include <cuda_bf16.h>
#include <cstdint>
#include <math.h>

// ============================================================================
// AutoEncoder via mma.sync (HMMA, PTX-portable on sm_103), bf16 hi/lo split.
// R4: 4-stage cp.async ring, single __syncthreads per K-iteration.
// ============================================================================

#define BATCH 8192

__device__ __forceinline__ uint32_t smem_u32(const void* p) {
    uint32_t a;
    asm("{ .reg .u64 t; cvta.to.shared.u64 t, %1; cvt.u32.u64 %0, t; }"
        : "=r"(a) : "l"(p));
    return a;
}
__device__ __forceinline__ void cp_async16(uint32_t dst, const void* src) {
    asm volatile("cp.async.cg.shared.global [%0], [%1], 16;" :: "r"(dst), "l"(src));
}
__device__ __forceinline__ void cp_commit() {
    asm volatile("cp.async.commit_group;" ::: "memory");
}
template <int N> __device__ __forceinline__ void cp_wait() {
    asm volatile("cp.async.wait_group %0;" :: "n"(N) : "memory");
}
__device__ __forceinline__ void ldsm4(uint32_t* r, uint32_t a) {
    asm volatile("ldmatrix.sync.aligned.m8n8.x4.shared.b16 {%0,%1,%2,%3}, [%4];"
                 : "=r"(r[0]), "=r"(r[1]), "=r"(r[2]), "=r"(r[3]) : "r"(a));
}
__device__ __forceinline__ void mma16816(float* d, const uint32_t* a, const uint32_t* b) {
    asm volatile("mma.sync.aligned.m16n8k16.row.col.f32.bf16.bf16.f32 "
                 "{%0,%1,%2,%3}, {%4,%5,%6,%7}, {%8,%9}, {%0,%1,%2,%3};"
                 : "+f"(d[0]), "+f"(d[1]), "+f"(d[2]), "+f"(d[3])
                 : "r"(a[0]), "r"(a[1]), "r"(a[2]), "r"(a[3]),
                   "r"(b[0]), "r"(b[1]));
}
// 64B logical rows packed pairwise into 128B atoms + SW128 XOR swizzle.
__device__ __forceinline__ uint32_t tile_off(int r, int c) {
    uint32_t o = ((uint32_t)(r >> 1) << 7) + ((uint32_t)(r & 1) << 6) +
                 ((uint32_t)c << 4);
    return o ^ ((o >> 3) & 0x70);
}

// ---------------------------------------------------------------------------
// Device global scratch
// ---------------------------------------------------------------------------
__device__ __align__(16) __nv_bfloat16 g_bufA_h[(size_t)BATCH * 2048];
__device__ __align__(16) __nv_bfloat16 g_bufA_l[(size_t)BATCH * 2048];
__device__ __align__(16) __nv_bfloat16 g_bufB_h[(size_t)BATCH * 2048];
__device__ __align__(16) __nv_bfloat16 g_bufB_l[(size_t)BATCH * 2048];
__device__ __align__(16) __nv_bfloat16 g_ctrl_h[(size_t)BATCH * 64];
__device__ __align__(16) __nv_bfloat16 g_ctrl_l[(size_t)BATCH * 64];

#define OFF_We1 0u
#define OFF_We2 (OFF_We1 + 2048u*1024u)
#define OFF_We3 (OFF_We2 + 2048u*2048u)
#define OFF_Wd1 (OFF_We3 + 64u*2048u)
#define OFF_Wd2 (OFF_Wd1 + 2048u*64u)
#define OFF_Wd3 (OFF_Wd2 + 2048u*2048u)
#define W_TOTAL (OFF_Wd3 + 1024u*2048u)
__device__ __align__(16) __nv_bfloat16 g_Wh[W_TOTAL];
__device__ __align__(16) __nv_bfloat16 g_Wl[W_TOTAL];

// ---------------------------------------------------------------------------
// Prep kernels
// ---------------------------------------------------------------------------
__global__ void split_convert(const float* __restrict__ X,
                              __nv_bfloat16* __restrict__ H,
                              __nv_bfloat16* __restrict__ L, int n4) {
    int i = blockIdx.x * blockDim.x + threadIdx.x;
    if (i >= n4) return;
    float4 x = reinterpret_cast<const float4*>(X)[i];
    __nv_bfloat16 h0 = __float2bfloat16(x.x), h1 = __float2bfloat16(x.y);
    __nv_bfloat16 h2 = __float2bfloat16(x.z), h3 = __float2bfloat16(x.w);
    __nv_bfloat16 l0 = __float2bfloat16(x.x - __bfloat162float(h0));
    __nv_bfloat16 l1 = __float2bfloat16(x.y - __bfloat162float(h1));
    __nv_bfloat16 l2 = __float2bfloat16(x.z - __bfloat162float(h2));
    __nv_bfloat16 l3 = __float2bfloat16(x.w - __bfloat162float(h3));
    reinterpret_cast<__nv_bfloat162*>(H)[i * 2 + 0] = __halves2bfloat162(h0, h1);
    reinterpret_cast<__nv_bfloat162*>(H)[i * 2 + 1] = __halves2bfloat162(h2, h3);
    reinterpret_cast<__nv_bfloat162*>(L)[i * 2 + 0] = __halves2bfloat162(l0, l1);
    reinterpret_cast<__nv_bfloat162*>(L)[i * 2 + 1] = __halves2bfloat162(l2, l3);
}

__global__ void transpose_split(const float* __restrict__ W,
                                __nv_bfloat16* __restrict__ Th,
                                __nv_bfloat16* __restrict__ Tl, int K, int N) {
    __shared__ float t[32][33];
    int k0 = blockIdx.x * 32, n0 = blockIdx.y * 32;
    int tx = threadIdx.x, ty = threadIdx.y;
    for (int r = ty; r < 32; r += 8)
        t[r][tx] = W[(size_t)(k0 + r) * N + n0 + tx];
    __syncthreads();
    for (int r = ty; r < 32; r += 8) {
        float v = t[tx][r];
        size_t o = (size_t)(n0 + r) * K + k0 + tx;
        __nv_bfloat16 h = __float2bfloat16(v);
        Th[o] = h;
        Tl[o] = __float2bfloat16(v - __bfloat162float(h));
    }
}

// ---------------------------------------------------------------------------
// mma.sync GEMM, 4-stage pipeline, 1 sync/iter.
// OUTMODE: 0 = f32 only, 1 = bf16 hi/lo pair only, 2 = both
// ---------------------------------------------------------------------------
template <int BM, int BN, int WARPS_M, int WARPS_N, int OUTMODE>
__global__ __launch_bounds__(256, 1)
void gemm_mma(const __nv_bfloat16* __restrict__ Ah, const __nv_bfloat16* __restrict__ Al,
              const __nv_bfloat16* __restrict__ Bh, const __nv_bfloat16* __restrict__ Bl,
              const float* __restrict__ bias,
              float* __restrict__ Cf,
              __nv_bfloat16* __restrict__ Ch, __nv_bfloat16* __restrict__ Cl,
              int N, int K, int act)
{
    constexpr int BK = 32;
    constexpr int STAGES = 4;
    constexpr int WM = BM / WARPS_M, WN = BN / WARPS_N;
    constexpr int MW = WM / 16, NW = WN / 8;
    constexpr int ASZ = BM * 64;   // bytes per operand per stage (32 bf16/row)
    constexpr int BSZ = BN * 64;
    constexpr int SSZ = 2 * ASZ + 2 * BSZ;

    extern __shared__ __align__(128) char sm[];
    const uint32_t sb = smem_u32(sm);
    const int tid = threadIdx.x, wid = tid >> 5, lid = tid & 31;
    const int row0 = blockIdx.y * BM, col0 = blockIdx.x * BN;
    const int KT = K / BK;

    const int wm0 = (wid % WARPS_M) * WM;
    const int wn0 = (wid / WARPS_M) * WN;
    const int mat = lid >> 3, mr = lid & 7;

    float acc[MW][NW][4];
#pragma unroll
    for (int i = 0; i < MW; i++)
#pragma unroll
        for (int j = 0; j < NW; j++)
#pragma unroll
            for (int q = 0; q < 4; q++) acc[i][j][q] = 0.0f;

    auto load_stage = [&](int kt, int s) {
        const uint32_t st = sb + s * SSZ;
        const int k0 = kt * BK;
#pragma unroll
        for (int ch = tid; ch < BM * 4; ch += 256) {
            int r = ch >> 2, c = ch & 3;
            size_t g = (size_t)(row0 + r) * K + k0 + c * 8;
            uint32_t so = st + tile_off(r, c);
            cp_async16(so, Ah + g);
            cp_async16(so + ASZ, Al + g);
        }
#pragma unroll
        for (int ch = tid; ch < BN * 4; ch += 256) {
            int r = ch >> 2, c = ch & 3;
            size_t g = (size_t)(col0 + r) * K + k0 + c * 8;
            uint32_t so = st + 2 * ASZ + tile_off(r, c);
            cp_async16(so, Bh + g);
            cp_async16(so + BSZ, Bl + g);
        }
    };

    int arow[MW], brow[NW / 2];
#pragma unroll
    for (int i = 0; i < MW; i++) arow[i] = wm0 + i * 16 + (mat & 1) * 8 + mr;
#pragma unroll
    for (int j = 0; j < NW / 2; j++) brow[j] = wn0 + j * 16 + (mat >> 1) * 8 + mr;

    // prologue: stages 0..2 (empty commits keep group arithmetic exact)
#pragma unroll
    for (int p = 0; p < STAGES - 1; p++) {
        if (p < KT) load_stage(p, p);
        cp_commit();
    }

    for (int kt = 0; kt < KT; kt++) {
        cp_wait<STAGES - 2>();
        __syncthreads();

        // issue stage kt+3 (slot == (kt-1)%4, consumed before this barrier)
        if (kt + STAGES - 1 < KT) load_stage(kt + STAGES - 1, (kt + STAGES - 1) & 3);
        cp_commit();

        const int s = kt & 3;
        const uint32_t stA  = sb + s * SSZ;
        const uint32_t stAl = stA + ASZ;
        const uint32_t stB  = stA + 2 * ASZ;
        const uint32_t stBl = stB + BSZ;

#pragma unroll
        for (int ks = 0; ks < 2; ks++) {
            uint32_t ah[MW][4], al[MW][4], bh[NW][2], bl[NW][2];
#pragma unroll
            for (int i = 0; i < MW; i++) {
                uint32_t off = tile_off(arow[i], 2 * ks + (mat >> 1));
                ldsm4(ah[i], stA + off);
                ldsm4(al[i], stAl + off);
            }
#pragma unroll
            for (int j = 0; j < NW / 2; j++) {
                uint32_t off = tile_off(brow[j], 2 * ks + (mat & 1));
                uint32_t t[4];
                ldsm4(t, stB + off);
                bh[2 * j][0] = t[0]; bh[2 * j][1] = t[1];
                bh[2 * j + 1][0] = t[2]; bh[2 * j + 1][1] = t[3];
                ldsm4(t, stBl + off);
                bl[2 * j][0] = t[0]; bl[2 * j][1] = t[1];
                bl[2 * j + 1][0] = t[2]; bl[2 * j + 1][1] = t[3];
            }
#pragma unroll
            for (int i = 0; i < MW; i++)
#pragma unroll
                for (int j = 0; j < NW; j++) {
                    mma16816(acc[i][j], ah[i], bh[j]);  // hh
                    mma16816(acc[i][j], ah[i], bl[j]);  // hl
                    mma16816(acc[i][j], al[i], bh[j]);  // lh
                }
        }
    }

    // ---- epilogue ----
    const int lm = lid >> 2, ln2 = (lid & 3) * 2;
#pragma unroll
    for (int i = 0; i < MW; i++)
#pragma unroll
        for (int j = 0; j < NW; j++)
#pragma unroll
            for (int h = 0; h < 2; h++) {
                int gm = row0 + wm0 + i * 16 + h * 8 + lm;
                int gn = col0 + wn0 + j * 8 + ln2;
                float v0 = acc[i][j][2 * h + 0] + __ldg(bias + gn);
                float v1 = acc[i][j][2 * h + 1] + __ldg(bias + gn + 1);
                if (act == 1) { v0 = fmaxf(v0, 0.f); v1 = fmaxf(v1, 0.f); }
                else if (act == 2) {
                    v0 = 1.0f / (1.0f + expf(-v0));
                    v1 = 1.0f / (1.0f + expf(-v1));
                }
                size_t o = (size_t)gm * N + gn;
                if (OUTMODE == 0 || OUTMODE == 2)
                    *reinterpret_cast<float2*>(Cf + o) = make_float2(v0, v1);
                if (OUTMODE == 1 || OUTMODE == 2) {
                    __nv_bfloat16 h0 = __float2bfloat16(v0);
                    __nv_bfloat16 h1 = __float2bfloat16(v1);
                    __nv_bfloat16 l0 = __float2bfloat16(v0 - __bfloat162float(h0));
                    __nv_bfloat16 l1 = __float2bfloat16(v1 - __bfloat162float(h1));
                    *reinterpret_cast<__nv_bfloat162*>(Ch + o) = __halves2bfloat162(h0, h1);
                    *reinterpret_cast<__nv_bfloat162*>(Cl + o) = __halves2bfloat162(l0, l1);
                }
            }
}

// ---------------------------------------------------------------------------
// Host launch
// ---------------------------------------------------------------------------
extern "C" void kernel_launch(void* const* d_in, const int* in_sizes, int n_in,
                              void* d_out, int out_size) {
    const float* x   = (const float*)d_in[0];
    const float* We1 = (const float*)d_in[1];
    const float* be1 = (const float*)d_in[2];
    const float* We2 = (const float*)d_in[3];
    const float* be2 = (const float*)d_in[4];
    const float* We3 = (const float*)d_in[5];
    const float* be3 = (const float*)d_in[6];
    const float* Wd1 = (const float*)d_in[7];
    const float* bd1 = (const float*)d_in[8];
    const float* Wd2 = (const float*)d_in[9];
    const float* bd2 = (const float*)d_in[10];
    const float* Wd3 = (const float*)d_in[11];
    const float* bd3 = (const float*)d_in[12];

    float* out = (float*)d_out;
    float* control = out;
    float* state   = out + (size_t)BATCH * 64;

    __nv_bfloat16 *bufAh, *bufAl, *bufBh, *bufBl, *ctrlh, *ctrll, *Wh, *Wl;
    cudaGetSymbolAddress((void**)&bufAh, g_bufA_h);
    cudaGetSymbolAddress((void**)&bufAl, g_bufA_l);
    cudaGetSymbolAddress((void**)&bufBh, g_bufB_h);
    cudaGetSymbolAddress((void**)&bufBl, g_bufB_l);
    cudaGetSymbolAddress((void**)&ctrlh, g_ctrl_h);
    cudaGetSymbolAddress((void**)&ctrll, g_ctrl_l);
    cudaGetSymbolAddress((void**)&Wh, g_Wh);
    cudaGetSymbolAddress((void**)&Wl, g_Wl);

    constexpr int SMEM_BIG   = 4 * (2 * 128 * 64 + 2 * 128 * 64);  // 131072
    constexpr int SMEM_SMALL = 4 * (2 * 64 * 64 + 2 * 64 * 64);    // 65536
    cudaFuncSetAttribute(gemm_mma<128,128,4,2,0>, cudaFuncAttributeMaxDynamicSharedMemorySize, SMEM_BIG);
    cudaFuncSetAttribute(gemm_mma<128,128,4,2,1>, cudaFuncAttributeMaxDynamicSharedMemorySize, SMEM_BIG);
    cudaFuncSetAttribute(gemm_mma<64,64,4,2,2>,   cudaFuncAttributeMaxDynamicSharedMemorySize, SMEM_SMALL);

    {
        int n4 = BATCH * 1024 / 4;
        split_convert<<<(n4 + 255) / 256, 256>>>(x, bufBh, bufBl, n4);
    }
    dim3 tb(32, 8);
    transpose_split<<<dim3(1024/32, 2048/32), tb>>>(We1, Wh + OFF_We1, Wl + OFF_We1, 1024, 2048);
    transpose_split<<<dim3(2048/32, 2048/32), tb>>>(We2, Wh + OFF_We2, Wl + OFF_We2, 2048, 2048);
    transpose_split<<<dim3(2048/32, 64/32),   tb>>>(We3, Wh + OFF_We3, Wl + OFF_We3, 2048, 64);
    transpose_split<<<dim3(64/32, 2048/32),   tb>>>(Wd1, Wh + OFF_Wd1, Wl + OFF_Wd1, 64, 2048);
    transpose_split<<<dim3(2048/32, 2048/32), tb>>>(Wd2, Wh + OFF_Wd2, Wl + OFF_Wd2, 2048, 2048);
    transpose_split<<<dim3(2048/32, 1024/32), tb>>>(Wd3, Wh + OFF_Wd3, Wl + OFF_Wd3, 2048, 1024);

    gemm_mma<128,128,4,2,1><<<dim3(16, 64), 256, SMEM_BIG>>>(
        bufBh, bufBl, Wh + OFF_We1, Wl + OFF_We1, be1,
        nullptr, bufAh, bufAl, 2048, 1024, 1);
    gemm_mma<128,128,4,2,1><<<dim3(16, 64), 256, SMEM_BIG>>>(
        bufAh, bufAl, Wh + OFF_We2, Wl + OFF_We2, be2,
        nullptr, bufBh, bufBl, 2048, 2048, 1);
    gemm_mma<64,64,4,2,2><<<dim3(1, 128), 256, SMEM_SMALL>>>(
        bufBh, bufBl, Wh + OFF_We3, Wl + OFF_We3, be3,
        control, ctrlh, ctrll, 64, 2048, 2);
    gemm_mma<128,128,4,2,1><<<dim3(16, 64), 256, SMEM_BIG>>>(
        ctrlh, ctrll, Wh + OFF_Wd1, Wl + OFF_Wd1, bd1,
        nullptr, bufAh, bufAl, 2048, 64, 1);
    gemm_mma<128,128,4,2,1><<<dim3(16, 64), 256, SMEM_BIG>>>(
        bufAh, bufAl, Wh + OFF_Wd2, Wl + OFF_Wd2, bd2,
        nullptr, bufBh, bufBl, 2048, 2048, 1);
    gemm_mma<128,128,4,2,0><<<dim3(8, 64), 256, SMEM_BIG>>>(
        bufBh, bufBl, Wh + OFF_Wd3, Wl + OFF_Wd3, bd3,
        state, nullptr, nullptr, 1024, 2048, 0);

    (void)in_sizes; (void)n_in; (void)out_size;
}